// round 7
// baseline (speedup 1.0000x reference)
#include <cuda_runtime.h>
#include <math.h>

#define NBLK 128
#define TPB  256
typedef unsigned long long ull;

// ---------------- device scratch ----------------
__device__ float g_h1[2][256 * 256];   // [u][b]
__device__ float g_h2[2][256 * 256];   // [u][b]
__device__ float g_last[256 * 256];    // [b][u]
__device__ float g_y[256 * 256];       // [b][j]
__device__ float g_emb[256 * 256 * 8]; // [t][b][e]
__device__ unsigned g_bar;

struct SmemLayout {
    float Wh0[256 * 32];   // [k][c], c = unit*4 + gate
    float Wi1[256 * 32];
    float Wh1[256 * 32];
    float Wi0[8 * 32];
    float b0[32];
    float b1[32];
    float hsA[256 * 64];   // staged h1 tile [k][b_local]; also reduce scratch A
    float hsB[256 * 64];   // staged h2 tile; also reduce scratch B
};

// ---------------- packed f32x2 helpers ----------------
__device__ __forceinline__ ull pk(float a, float b) {
    ull r; asm("mov.b64 %0, {%1,%2};" : "=l"(r) : "f"(a), "f"(b)); return r;
}
__device__ __forceinline__ void unpk(ull v, float& a, float& b) {
    asm("mov.b64 {%0,%1}, %2;" : "=f"(a), "=f"(b) : "l"(v));
}
__device__ __forceinline__ void fma2(ull& acc, ull a, ull b) {
    asm("fma.rn.f32x2 %0, %1, %2, %0;" : "+l"(acc) : "l"(a), "l"(b));
}
__device__ __forceinline__ void add2(ull& acc, ull b) {
    asm("add.rn.f32x2 %0, %0, %1;" : "+l"(acc) : "l"(b));
}

__device__ __forceinline__ float sigf(float x) { return 1.f / (1.f + __expf(-x)); }
__device__ __forceinline__ float tanha(float x) { return 2.f * sigf(2.f * x) - 1.f; }

// ---------------- grid barrier ----------------
__device__ __forceinline__ void grid_sync(unsigned& gen) {
    __syncthreads();
    if (threadIdx.x == 0) {
        __threadfence();
        atomicAdd(&g_bar, 1u);
        gen += NBLK;
        unsigned v;
        do {
            asm volatile("ld.acquire.gpu.global.u32 %0, [%1];" : "=r"(v) : "l"(&g_bar));
        } while (v < gen);
    }
    __syncthreads();
}

// ---------------- cp.async helpers ----------------
__device__ __forceinline__ void cpa16(float* dst_smem, const float* src) {
    unsigned d = (unsigned)__cvta_generic_to_shared(dst_smem);
    asm volatile("cp.async.cg.shared.global [%0], [%1], 16;" :: "r"(d), "l"(src));
}
__device__ __forceinline__ void cpa_commit() { asm volatile("cp.async.commit_group;"); }
#define CPA_WAIT(N) asm volatile("cp.async.wait_group %0;" :: "n"(N))

// stage: global [u][b] slice (cols bg*64.., all 256 u) -> smem [k][64], 256 threads
__device__ __forceinline__ void stage_cg(float* __restrict__ hs,
                                         const float* __restrict__ src,
                                         int bg, int tid) {
    const float* base = src + bg * 64;
#pragma unroll
    for (int i = 0; i < 16; i++) {
        int idx = i * 256 + tid;        // 4096 float4 total
        int k = idx >> 4;
        int seg = (idx & 15) * 4;
        cpa16(hs + k * 64 + seg, base + k * 256 + seg);
    }
}

// ---------------- half-K tile GEMM: thread = 4 rows x 1 unit over 128 k ----------------
__device__ __forceinline__ void gemm8h(const float* __restrict__ sW,
                                       const float* __restrict__ hs,
                                       int txc, int txb, int koff, ull acc[8]) {
    const float4* wp = (const float4*)(sW + koff * 32 + 4 * txc);  // stride 8 f4/k
    const float4* hp = (const float4*)(hs + koff * 64 + 4 * txb);  // stride 16 f4/k
#pragma unroll 8
    for (int k = 0; k < 128; k++) {
        float4 w = wp[k * 8];
        float4 h = hp[k * 16];
        ull w01 = pk(w.x, w.y), w23 = pk(w.z, w.w);
        ull d0 = pk(h.x, h.x), d1 = pk(h.y, h.y);
        ull d2 = pk(h.z, h.z), d3 = pk(h.w, h.w);
        fma2(acc[0], w01, d0); fma2(acc[1], w23, d0);
        fma2(acc[2], w01, d1); fma2(acc[3], w23, d1);
        fma2(acc[4], w01, d2); fma2(acc[5], w23, d2);
        fma2(acc[6], w01, d3); fma2(acc[7], w23, d3);
    }
}

// ---------------- combined split-K reduction ----------------
// a0 final lands in kh=0 (L0 team), a1 final lands in kh=1 (L1 team).
// Uses hsA/hsB (dead after gemms) as scratch; leading bar orders gemm reads.
__device__ __forceinline__ void reduce_both(float* bufA, float* bufB,
                                            ull a0[8], ull a1[8], int kh, int w) {
    ull* rA = (ull*)bufA;
    ull* rB = (ull*)bufB;
    __syncthreads();
    if (kh) {
#pragma unroll
        for (int i = 0; i < 8; i++) rA[i * 128 + w] = a0[i];
    } else {
#pragma unroll
        for (int i = 0; i < 8; i++) rB[i * 128 + w] = a1[i];
    }
    __syncthreads();
    if (!kh) {
#pragma unroll
        for (int i = 0; i < 8; i++) add2(a0[i], rA[i * 128 + w]);
    } else {
#pragma unroll
        for (int i = 0; i < 8; i++) add2(a1[i], rB[i * 128 + w]);
    }
}

__device__ __forceinline__ float lstm_h(ull g01, ull g23, float& cs) {
    float iv, fv, gv, ov;
    unpk(g01, iv, fv); unpk(g23, gv, ov);
    cs = sigf(fv) * cs + sigf(iv) * tanha(gv);
    return sigf(ov) * tanha(cs);
}

// x-part of L0 gates for timestep t (4 batch rows rb..rb+3, unit txc)
__device__ __forceinline__ void xpart(const float* __restrict__ Wi0,
                                      int t, int rb, int txc, ull a[8]) {
    const float4* ep = (const float4*)(g_emb + (t * 256 + rb) * 8);
    float xv[4][8];
#pragma unroll
    for (int r = 0; r < 4; r++) {
        float4 u0 = ep[2 * r], u1 = ep[2 * r + 1];
        xv[r][0] = u0.x; xv[r][1] = u0.y; xv[r][2] = u0.z; xv[r][3] = u0.w;
        xv[r][4] = u1.x; xv[r][5] = u1.y; xv[r][6] = u1.z; xv[r][7] = u1.w;
    }
#pragma unroll
    for (int e = 0; e < 8; e++) {
        float4 wv = *(const float4*)(&Wi0[e * 32 + 4 * txc]);
        ull w01 = pk(wv.x, wv.y), w23 = pk(wv.z, wv.w);
#pragma unroll
        for (int r = 0; r < 4; r++) {
            ull xd = pk(xv[r][e], xv[r][e]);
            fma2(a[2 * r], w01, xd);
            fma2(a[2 * r + 1], w23, xd);
        }
    }
}

// ---------------- prep: embedding gather + barrier reset ----------------
__global__ void prep_kernel(const int* __restrict__ tokens,
                            const float* __restrict__ emb) {
    int idx = blockIdx.x * 256 + threadIdx.x;  // 0..65535
    if (idx == 0) g_bar = 0;
    int b = idx >> 8, t = idx & 255;
    int tok = tokens[b * 256 + t];
    const float4* e = (const float4*)(emb + tok * 8);
    float4* d = (float4*)(g_emb + (t * 256 + b) * 8);
    d[0] = e[0];
    d[1] = e[1];
}

// ---------------- persistent LSTM kernel ----------------
extern __shared__ float smem_raw[];

__global__ void __launch_bounds__(TPB, 1)
lstm_kernel(const int* __restrict__ lengths,
            const float* __restrict__ w_ih0, const float* __restrict__ w_hh0,
            const float* __restrict__ b_ih0, const float* __restrict__ b_hh0,
            const float* __restrict__ w_ih1, const float* __restrict__ w_hh1,
            const float* __restrict__ b_ih1, const float* __restrict__ b_hh1,
            const float* __restrict__ ff_w, const float* __restrict__ ff_b,
            const float* __restrict__ bn_g, const float* __restrict__ bn_b,
            float* __restrict__ out) {
    SmemLayout* S = (SmemLayout*)smem_raw;
    const int tid = threadIdx.x;
    const int bid = blockIdx.x;
    const int bg = bid >> 5;     // batch group 0..3 (64 rows)
    const int ug = bid & 31;     // unit group 0..31 (8 units)
    const int kh = tid >> 7;     // k-half team: 0 -> k[0,128) + L0 cell; 1 -> k[128,256) + L1 cell
    const int w  = tid & 127;
    const int txc = w & 7;       // unit within group
    const int txb = w >> 3;      // 0..15 -> rows 4*txb..4*txb+3
    const int koff = kh * 128;
    const int rb = bg * 64 + 4 * txb;
    const int u = ug * 8 + txc;

    // --- load + permute weights into SMEM ---
    for (int idx = tid; idx < 32 * 256; idx += TPB) {
        int c = idx & 31, k = idx >> 5;
        int uu = c >> 2, g = c & 3;
        int row = g * 256 + ug * 8 + uu;
        S->Wh0[k * 32 + c] = w_hh0[row * 256 + k];
        S->Wi1[k * 32 + c] = w_ih1[row * 256 + k];
        S->Wh1[k * 32 + c] = w_hh1[row * 256 + k];
    }
    if (tid < 8 * 32) {
        int c = tid & 31, e = tid >> 5;
        int uu = c >> 2, g = c & 3;
        int row = g * 256 + ug * 8 + uu;
        S->Wi0[e * 32 + c] = w_ih0[row * 8 + e];
    }
    if (tid < 32) {
        int uu = tid >> 2, g = tid & 3;
        int row = g * 256 + ug * 8 + uu;
        S->b0[tid] = b_ih0[row] + b_hh0[row];
        S->b1[tid] = b_ih1[row] + b_hh1[row];
    }
    // h2(-1) = 0 lives in g_h2[1] (read at phase 0)
    if (!kh) {
        *(float4*)(&g_h2[1][u * 256 + rb]) = make_float4(0.f, 0.f, 0.f, 0.f);
    }

    int4 ln4 = *(const int4*)(lengths + rb);
    int ln[4] = {ln4.x, ln4.y, ln4.z, ln4.w};
    float c1s[4] = {0.f, 0.f, 0.f, 0.f};
    float c2s[4] = {0.f, 0.f, 0.f, 0.f};
    unsigned gen = 0;
    __syncthreads();   // smem biases ready for prologue

    ull bi01_0 = pk(S->b0[4 * txc + 0], S->b0[4 * txc + 1]);
    ull bi23_0 = pk(S->b0[4 * txc + 2], S->b0[4 * txc + 3]);
    ull bi01_1 = pk(S->b1[4 * txc + 0], S->b1[4 * txc + 1]);
    ull bi23_1 = pk(S->b1[4 * txc + 2], S->b1[4 * txc + 3]);
    const ull Z = 0ull;

    // ---------- prologue: h1(0) = cell(x(0), 0)  (no cross-block sum needed) ----------
    if (!kh) {
        ull a0[8];
        a0[0] = a0[2] = a0[4] = a0[6] = bi01_0;
        a0[1] = a0[3] = a0[5] = a0[7] = bi23_0;
        xpart(S->Wi0, 0, rb, txc, a0);
        float h1v[4];
#pragma unroll
        for (int r = 0; r < 4; r++)
            h1v[r] = lstm_h(a0[2 * r], a0[2 * r + 1], c1s[r]);
        *(float4*)(&g_h1[0][u * 256 + rb]) =
            make_float4(h1v[0], h1v[1], h1v[2], h1v[3]);
    }
    grid_sync(gen);

    // ---------- main loop: phase p computes h1(p+1) and h2(p) ----------
    for (int p = 0; p < 255; p++) {
        const int cb = p & 1;   // h1(p) in g_h1[cb], h2(p-1) in g_h2[cb^1]

        stage_cg(S->hsA, g_h1[cb], bg, tid);      // h1(p)    group 0
        cpa_commit();
        stage_cg(S->hsB, g_h2[cb ^ 1], bg, tid);  // h2(p-1)  group 1
        cpa_commit();

        ull a0[8], a1[8];
        if (!kh) {
            a0[0] = a0[2] = a0[4] = a0[6] = bi01_0;
            a0[1] = a0[3] = a0[5] = a0[7] = bi23_0;
            xpart(S->Wi0, p + 1, rb, txc, a0);    // x(p+1), overlaps stage latency
#pragma unroll
            for (int i = 0; i < 8; i++) a1[i] = Z;
        } else {
#pragma unroll
            for (int i = 0; i < 8; i++) a0[i] = Z;
            a1[0] = a1[2] = a1[4] = a1[6] = bi01_1;
            a1[1] = a1[3] = a1[5] = a1[7] = bi23_1;
        }

        CPA_WAIT(1);
        __syncthreads();                          // hsA (h1(p)) ready
        gemm8h(S->Wh0, S->hsA, txc, txb, koff, a0);
        gemm8h(S->Wi1, S->hsA, txc, txb, koff, a1);

        CPA_WAIT(0);
        __syncthreads();                          // hsB (h2(p-1)) ready
        gemm8h(S->Wh1, S->hsB, txc, txb, koff, a1);

        reduce_both(S->hsA, S->hsB, a0, a1, kh, w);

        if (!kh) {
            float h1v[4];
#pragma unroll
            for (int r = 0; r < 4; r++)
                h1v[r] = lstm_h(a0[2 * r], a0[2 * r + 1], c1s[r]);
            *(float4*)(&g_h1[cb ^ 1][u * 256 + rb]) =
                make_float4(h1v[0], h1v[1], h1v[2], h1v[3]);   // h1(p+1)
        } else {
            float h2v[4];
#pragma unroll
            for (int r = 0; r < 4; r++)
                h2v[r] = lstm_h(a1[2 * r], a1[2 * r + 1], c2s[r]);
            *(float4*)(&g_h2[cb][u * 256 + rb]) =
                make_float4(h2v[0], h2v[1], h2v[2], h2v[3]);   // h2(p)
#pragma unroll
            for (int r = 0; r < 4; r++)
                if (p == ln[r] - 1) g_last[(rb + r) * 256 + u] = h2v[r];
        }

        grid_sync(gen);
    }

    // ---------- epilogue: h2(255) from h1(255) (buf 1) and h2(254) (buf 0) ----------
    {
        stage_cg(S->hsA, g_h1[1], bg, tid);
        cpa_commit();
        stage_cg(S->hsB, g_h2[0], bg, tid);
        cpa_commit();

        ull a1[8];
        if (kh) {
            a1[0] = a1[2] = a1[4] = a1[6] = bi01_1;
            a1[1] = a1[3] = a1[5] = a1[7] = bi23_1;
        } else {
#pragma unroll
            for (int i = 0; i < 8; i++) a1[i] = Z;
        }

        CPA_WAIT(1);
        __syncthreads();
        gemm8h(S->Wi1, S->hsA, txc, txb, koff, a1);
        CPA_WAIT(0);
        __syncthreads();
        gemm8h(S->Wh1, S->hsB, txc, txb, koff, a1);

        ull* rB = (ull*)S->hsB;
        __syncthreads();
        if (!kh) {
#pragma unroll
            for (int i = 0; i < 8; i++) rB[i * 128 + w] = a1[i];
        }
        __syncthreads();
        if (kh) {
#pragma unroll
            for (int i = 0; i < 8; i++) add2(a1[i], rB[i * 128 + w]);
            float h2v[4];
#pragma unroll
            for (int r = 0; r < 4; r++)
                h2v[r] = lstm_h(a1[2 * r], a1[2 * r + 1], c2s[r]);
#pragma unroll
            for (int r = 0; r < 4; r++)
                if (ln[r] == 256) g_last[(rb + r) * 256 + u] = h2v[r];
        }
    }

    grid_sync(gen);

    // ================= y = relu(last) @ ff_w^T + ff_b =================
    // block handles batch rows 2*bid, 2*bid+1; thread = col tid (256 cols)
    {
        float* sv = S->hsA;
        int br0 = 2 * bid, br1 = 2 * bid + 1;
        sv[tid]       = fmaxf(g_last[br0 * 256 + tid], 0.f);
        sv[256 + tid] = fmaxf(g_last[br1 * 256 + tid], 0.f);
        __syncthreads();
        float a0 = ff_b[tid], a1 = a0;
        const float4* wr = (const float4*)(ff_w + tid * 256);
        const float4* h0 = (const float4*)sv;
        const float4* h1 = (const float4*)(sv + 256);
#pragma unroll 4
        for (int k4 = 0; k4 < 64; k4++) {
            float4 wv = wr[k4];
            float4 ha = h0[k4], hb = h1[k4];
            a0 += wv.x * ha.x + wv.y * ha.y + wv.z * ha.z + wv.w * ha.w;
            a1 += wv.x * hb.x + wv.y * hb.y + wv.z * hb.z + wv.w * hb.w;
        }
        g_y[br0 * 256 + tid] = a0;
        g_y[br1 * 256 + tid] = a1;
    }

    grid_sync(gen);

    // ================= BatchNorm over batch axis =================
    // block handles cols 2*bid, 2*bid+1; thread = batch row tid (256 rows)
    {
        float* red = S->hsA;
        for (int r = 0; r < 2; r++) {
            int j = 2 * bid + r;
            float v = g_y[tid * 256 + j];
            __syncthreads();
            red[tid] = v;
            __syncthreads();
            for (int s = 128; s > 0; s >>= 1) {
                if (tid < s) red[tid] += red[tid + s];
                __syncthreads();
            }
            float mean = red[0] * (1.f / 256.f);
            __syncthreads();
            float d = v - mean;
            red[tid] = d * d;
            __syncthreads();
            for (int s = 128; s > 0; s >>= 1) {
                if (tid < s) red[tid] += red[tid + s];
                __syncthreads();
            }
            float inv = rsqrtf(red[0] * (1.f / 256.f) + 1e-5f);
            __syncthreads();
            out[tid * 256 + j] = bn_g[j] * d * inv + bn_b[j];
        }
    }
}

// ---------------- launch ----------------
extern "C" void kernel_launch(void* const* d_in, const int* in_sizes, int n_in,
                              void* d_out, int out_size) {
    const int*   tokens    = (const int*)d_in[0];
    const int*   lengths   = (const int*)d_in[1];
    const float* embedding = (const float*)d_in[2];
    const float* w_ih0     = (const float*)d_in[3];
    const float* w_hh0     = (const float*)d_in[4];
    const float* b_ih0     = (const float*)d_in[5];
    const float* b_hh0     = (const float*)d_in[6];
    const float* w_ih1     = (const float*)d_in[7];
    const float* w_hh1     = (const float*)d_in[8];
    const float* b_ih1     = (const float*)d_in[9];
    const float* b_hh1     = (const float*)d_in[10];
    const float* ff_w      = (const float*)d_in[11];
    const float* ff_b      = (const float*)d_in[12];
    const float* bn_g      = (const float*)d_in[13];
    const float* bn_b      = (const float*)d_in[14];
    float* out = (float*)d_out;

    cudaFuncSetAttribute(lstm_kernel, cudaFuncAttributeMaxDynamicSharedMemorySize,
                         (int)sizeof(SmemLayout));

    prep_kernel<<<256, 256>>>(tokens, embedding);
    lstm_kernel<<<NBLK, TPB, sizeof(SmemLayout)>>>(
        lengths, w_ih0, w_hh0, b_ih0, b_hh0,
        w_ih1, w_hh1, b_ih1, b_hh1,
        ff_w, ff_b, bn_g, bn_b, out);
}

// round 9
// speedup vs baseline: 1.9993x; 1.9993x over previous
#include <cuda_runtime.h>
#include <cuda_bf16.h>
#include <math.h>
#include <stdint.h>

#define TPB  256
#define NBLK 128

// ---- smem byte offsets (from dynamic smem base) ----
#define OFF_W    0        // 6 x 16384: Wh0hi,Wh0lo,Wi1hi,Wi1lo,Wh1hi,Wh1lo (frag order)
#define OFF_H1   98304    // h1 A-frags: hi 32768 + lo 32768
#define OFF_H2   163840   // h2 A-frags: hi + lo ; D-scratch overlays here
#define OFF_WI0  229376   // 8*32 float
#define OFF_B0   230400   // 32 float
#define OFF_B1   230528   // 32 float
#define SMEM_DYN 230656

// ---------------- device scratch ----------------
// h in A-fragment order: [parity][bg*8192 + (kc*4+mc)*128 + lane*4 + reg] (b32, bf16x2)
__device__ unsigned g_h1hi[2][32768];
__device__ unsigned g_h1lo[2][32768];
__device__ unsigned g_h2hi[2][32768];
__device__ unsigned g_h2lo[2][32768];
__device__ float    g_last[256 * 256];      // [b][u]
__device__ float    g_y[256 * 256];         // [b][j]
__device__ float    g_emb[256 * 256 * 8];   // [t][b][e]
__device__ unsigned g_barG[4][32];          // per-batch-group barriers (padded lines)
__device__ unsigned g_barF;                 // full-grid barrier

// ---------------- helpers ----------------
__device__ __forceinline__ float sigf(float x) { return 1.f / (1.f + __expf(-x)); }
__device__ __forceinline__ float tanha(float x) { return 2.f * sigf(2.f * x) - 1.f; }

__device__ __forceinline__ void hilo_pack(float v0, float v1, unsigned& hi, unsigned& lo) {
    asm("cvt.rn.bf16x2.f32 %0, %1, %2;" : "=r"(hi) : "f"(v1), "f"(v0));  // v0 low
    float l0 = v0 - __uint_as_float(hi << 16);
    float l1 = v1 - __uint_as_float(hi & 0xFFFF0000u);
    asm("cvt.rn.bf16x2.f32 %0, %1, %2;" : "=r"(lo) : "f"(l1), "f"(l0));
}

__device__ __forceinline__ void mma16816(float* acc, uint4 A, unsigned b0, unsigned b1) {
    asm("mma.sync.aligned.m16n8k16.row.col.f32.bf16.bf16.f32 "
        "{%0,%1,%2,%3}, {%4,%5,%6,%7}, {%8,%9}, {%0,%1,%2,%3};"
        : "+f"(acc[0]), "+f"(acc[1]), "+f"(acc[2]), "+f"(acc[3])
        : "r"(A.x), "r"(A.y), "r"(A.z), "r"(A.w), "r"(b0), "r"(b1));
}

__device__ __forceinline__ void cpa16(void* dst_smem, const void* src) {
    unsigned d = (unsigned)__cvta_generic_to_shared(dst_smem);
    asm volatile("cp.async.cg.shared.global [%0], [%1], 16;" :: "r"(d), "l"(src));
}
__device__ __forceinline__ void cpa_commit() { asm volatile("cp.async.commit_group;"); }
#define CPA_WAIT(N) asm volatile("cp.async.wait_group %0;" :: "n"(N))

__device__ __forceinline__ void bar_sync(unsigned* ctr, unsigned& gen, int n) {
    __syncthreads();
    if (threadIdx.x == 0) {
        __threadfence();
        atomicAdd(ctr, 1u);
        gen += (unsigned)n;
        unsigned v;
        do { asm volatile("ld.acquire.gpu.global.u32 %0, [%1];" : "=r"(v) : "l"(ctr)); }
        while (v < gen);
    }
    __syncthreads();
}

// ---------------- prep: embedding gather + barrier reset ----------------
__global__ void prep_kernel(const int* __restrict__ tokens,
                            const float* __restrict__ emb) {
    int idx = blockIdx.x * 256 + threadIdx.x;
    if (idx < 4) g_barG[idx][0] = 0;
    if (idx == 4) g_barF = 0;
    int b = idx >> 8, t = idx & 255;
    int tok = tokens[b * 256 + t];
    const float4* e = (const float4*)(emb + tok * 8);
    float4* d = (float4*)(g_emb + (t * 256 + b) * 8);
    d[0] = e[0]; d[1] = e[1];
}

// ---------------- persistent LSTM kernel (mma.sync tensor cores) ----------------
extern __shared__ char smem_raw[];

__global__ void __launch_bounds__(TPB, 1)
lstm_kernel(const int* __restrict__ lengths,
            const float* __restrict__ w_ih0, const float* __restrict__ w_hh0,
            const float* __restrict__ b_ih0, const float* __restrict__ b_hh0,
            const float* __restrict__ w_ih1, const float* __restrict__ w_hh1,
            const float* __restrict__ b_ih1, const float* __restrict__ b_hh1,
            const float* __restrict__ ff_w, const float* __restrict__ ff_b,
            const float* __restrict__ bn_g, const float* __restrict__ bn_b,
            float* __restrict__ out) {
    char* SB = smem_raw;
    const int tid = threadIdx.x;
    const int bid = blockIdx.x;
    const int bg = bid >> 5;      // batch group: rows bg*64 .. +63
    const int ug = bid & 31;      // unit group: units ug*8 .. +7
    const int wid = tid >> 5, lane = tid & 31;
    const int wm = wid >> 1, wn = wid & 1;      // warp tile: rows wm*16, cols wn*16
    const int gID = lane >> 2, tig = lane & 3;
    const int bl = tid & 63, up = tid >> 6;     // pointwise: batch row bl, unit pair up
    const int b = bg * 64 + bl;

    float* sWi0 = (float*)(SB + OFF_WI0);
    float* sB0  = (float*)(SB + OFF_B0);
    float* sB1  = (float*)(SB + OFF_B1);

    // ---- pack weights into exact B-fragment order (bf16 hi/lo) ----
    // slot idx: kc*256 + wn*128 + lane*4 + j ; j = (n8half<<1)|breg
    {
        const float* srcs[3] = { w_hh0, w_ih1, w_hh1 };
#pragma unroll
        for (int m = 0; m < 3; m++) {
            const float* src = srcs[m];
            unsigned* dhi = (unsigned*)(SB + OFF_W + (2 * m) * 16384);
            unsigned* dlo = (unsigned*)(SB + OFF_W + (2 * m + 1) * 16384);
            for (int idx = tid; idx < 4096; idx += TPB) {
                int j = idx & 3, ln = (idx >> 2) & 31, wnn = (idx >> 7) & 1, kc = idx >> 8;
                int n_loc = wnn * 16 + ((j >> 1) << 3) + (ln >> 2);
                int k0 = kc * 16 + (ln & 3) * 2 + (j & 1) * 8;
                int row = (n_loc & 3) * 256 + ug * 8 + (n_loc >> 2);
                float w0 = src[row * 256 + k0], w1 = src[row * 256 + k0 + 1];
                __nv_bfloat16 h0 = __float2bfloat16(w0);
                __nv_bfloat16 h1 = __float2bfloat16(w1);
                __nv_bfloat16 l0 = __float2bfloat16(w0 - __bfloat162float(h0));
                __nv_bfloat16 l1 = __float2bfloat16(w1 - __bfloat162float(h1));
                dhi[idx] = ((unsigned)__bfloat16_as_ushort(h1) << 16) | __bfloat16_as_ushort(h0);
                dlo[idx] = ((unsigned)__bfloat16_as_ushort(l1) << 16) | __bfloat16_as_ushort(l0);
            }
        }
    }
    if (tid < 256) {
        int e = tid >> 5, c = tid & 31;
        int row = (c & 3) * 256 + ug * 8 + (c >> 2);
        sWi0[e * 32 + c] = w_ih0[row * 8 + e];
    }
    if (tid < 32) {
        int row = (tid & 3) * 256 + ug * 8 + (tid >> 2);
        sB0[tid] = b_ih0[row] + b_hh0[row];
        sB1[tid] = b_ih1[row] + b_hh1[row];
    }

    // per-thread h slot in A-frag global layout (same for h1/h2)
    const int kc_u = ug >> 1;
    const int row16 = bl & 15;
    const int slot = bg * 8192 + (kc_u * 4 + (bl >> 4)) * 128 +
                     ((row16 & 7) * 4 + up) * 4 + (row16 >> 3) + 2 * (ug & 1);

    // h2(-1) = 0 in parity-1 buffer
    g_h2hi[1][slot] = 0u;
    g_h2lo[1][slot] = 0u;

    const int myLen = lengths[b];
    float c1s0 = 0.f, c1s1 = 0.f, c2s0 = 0.f, c2s1 = 0.f;
    unsigned genG = 0, genF = 0;
    __syncthreads();   // smem weights/biases ready

    // ---- prologue: h1(0) = cell(x(0), 0) ----
    {
        float xp[8];
#pragma unroll
        for (int c = 0; c < 8; c++) xp[c] = sB0[up * 8 + c];
        const float4* ep = (const float4*)(g_emb + (0 * 256 + b) * 8);
        float4 e0 = ep[0], e1 = ep[1];
        float xs[8] = { e0.x, e0.y, e0.z, e0.w, e1.x, e1.y, e1.z, e1.w };
#pragma unroll
        for (int e = 0; e < 8; e++)
#pragma unroll
            for (int c = 0; c < 8; c++) xp[c] += xs[e] * sWi0[e * 32 + up * 8 + c];
        float cc0 = sigf(xp[0]) * tanha(xp[2]);
        float h10 = sigf(xp[3]) * tanha(cc0);
        float cc1 = sigf(xp[4]) * tanha(xp[6]);
        float h11 = sigf(xp[7]) * tanha(cc1);
        c1s0 = cc0; c1s1 = cc1;
        unsigned hi, lo;
        hilo_pack(h10, h11, hi, lo);
        g_h1hi[0][slot] = hi;
        g_h1lo[0][slot] = lo;
    }
    bar_sync(&g_barG[bg][0], genG, 32);

    const char* pA  = SB + OFF_H1 + wm * 512 + lane * 16;
    const char* pA2 = SB + OFF_H2 + wm * 512 + lane * 16;
    const char* pB  = SB + OFF_W + wn * 512 + lane * 16;

    // ---- main loop: phase p computes h1(p+1) and h2(p) ----
    for (int p = 0; p < 256; p++) {
        const int rp = p & 1;

        // stage h1(p) hi/lo (group 0) and h2(p-1) hi/lo (group 1)
        {
            const uint4* s1h = (const uint4*)(g_h1hi[rp] + bg * 8192);
            const uint4* s1l = (const uint4*)(g_h1lo[rp] + bg * 8192);
#pragma unroll
            for (int i = 0; i < 8; i++) {
                int ix = i * 256 + tid;
                cpa16(SB + OFF_H1 + ix * 16, s1h + ix);
                cpa16(SB + OFF_H1 + 32768 + ix * 16, s1l + ix);
            }
            cpa_commit();
            const uint4* s2h = (const uint4*)(g_h2hi[rp ^ 1] + bg * 8192);
            const uint4* s2l = (const uint4*)(g_h2lo[rp ^ 1] + bg * 8192);
#pragma unroll
            for (int i = 0; i < 8; i++) {
                int ix = i * 256 + tid;
                cpa16(SB + OFF_H2 + ix * 16, s2h + ix);
                cpa16(SB + OFF_H2 + 32768 + ix * 16, s2l + ix);
            }
            cpa_commit();
        }

        float D0[8], D1[8];
#pragma unroll
        for (int i = 0; i < 8; i++) { D0[i] = 0.f; D1[i] = 0.f; }

        CPA_WAIT(1);
        __syncthreads();              // h1 frags ready
#pragma unroll 4
        for (int kc = 0; kc < 16; kc++) {
            uint4 Ah = *(const uint4*)(pA + kc * 2048);
            uint4 Al = *(const uint4*)(pA + kc * 2048 + 32768);
            uint4 B0h = *(const uint4*)(pB + kc * 1024);
            uint4 B0l = *(const uint4*)(pB + 16384 + kc * 1024);
            uint4 B1h = *(const uint4*)(pB + 32768 + kc * 1024);
            uint4 B1l = *(const uint4*)(pB + 49152 + kc * 1024);
            mma16816(D0 + 0, Ah, B0h.x, B0h.y); mma16816(D0 + 4, Ah, B0h.z, B0h.w);
            mma16816(D1 + 0, Ah, B1h.x, B1h.y); mma16816(D1 + 4, Ah, B1h.z, B1h.w);
            mma16816(D0 + 0, Ah, B0l.x, B0l.y); mma16816(D0 + 4, Ah, B0l.z, B0l.w);
            mma16816(D1 + 0, Ah, B1l.x, B1l.y); mma16816(D1 + 4, Ah, B1l.z, B1l.w);
            mma16816(D0 + 0, Al, B0h.x, B0h.y); mma16816(D0 + 4, Al, B0h.z, B0h.w);
            mma16816(D1 + 0, Al, B1h.x, B1h.y); mma16816(D1 + 4, Al, B1h.z, B1h.w);
        }

        CPA_WAIT(0);
        __syncthreads();              // h2 frags ready
#pragma unroll 4
        for (int kc = 0; kc < 16; kc++) {
            uint4 Ah = *(const uint4*)(pA2 + kc * 2048);
            uint4 Al = *(const uint4*)(pA2 + kc * 2048 + 32768);
            uint4 B2h = *(const uint4*)(pB + 65536 + kc * 1024);
            uint4 B2l = *(const uint4*)(pB + 81920 + kc * 1024);
            mma16816(D1 + 0, Ah, B2h.x, B2h.y); mma16816(D1 + 4, Ah, B2h.z, B2h.w);
            mma16816(D1 + 0, Ah, B2l.x, B2l.y); mma16816(D1 + 4, Ah, B2l.z, B2l.w);
            mma16816(D1 + 0, Al, B2h.x, B2h.y); mma16816(D1 + 4, Al, B2h.z, B2h.w);
        }

        __syncthreads();              // all h2 reads done; overlay scratch
        {   // dump accumulators: scratch stride 36 floats
            float* scr0 = (float*)(SB + OFF_H2);
            float* scr1 = scr0 + 64 * 36;
            int r0 = wm * 16 + gID, c0 = wn * 16 + tig * 2;
            scr0[r0 * 36 + c0] = D0[0];       scr0[r0 * 36 + c0 + 1] = D0[1];
            scr0[(r0 + 8) * 36 + c0] = D0[2]; scr0[(r0 + 8) * 36 + c0 + 1] = D0[3];
            scr0[r0 * 36 + c0 + 8] = D0[4];   scr0[r0 * 36 + c0 + 9] = D0[5];
            scr0[(r0 + 8) * 36 + c0 + 8] = D0[6]; scr0[(r0 + 8) * 36 + c0 + 9] = D0[7];
            scr1[r0 * 36 + c0] = D1[0];       scr1[r0 * 36 + c0 + 1] = D1[1];
            scr1[(r0 + 8) * 36 + c0] = D1[2]; scr1[(r0 + 8) * 36 + c0 + 1] = D1[3];
            scr1[r0 * 36 + c0 + 8] = D1[4];   scr1[r0 * 36 + c0 + 9] = D1[5];
            scr1[(r0 + 8) * 36 + c0 + 8] = D1[6]; scr1[(r0 + 8) * 36 + c0 + 9] = D1[7];
        }
        __syncthreads();

        // ---- pointwise: thread owns (bl, units 2up, 2up+1) ----
        {
            const float* scr0 = (const float*)(SB + OFF_H2);
            const float* scr1 = scr0 + 64 * 36;
            // x-part for h1(p+1)
            int tx = (p < 255) ? p + 1 : 255;
            float xp[8];
#pragma unroll
            for (int c = 0; c < 8; c++) xp[c] = sB0[up * 8 + c];
            const float4* ep = (const float4*)(g_emb + (tx * 256 + b) * 8);
            float4 e0 = ep[0], e1 = ep[1];
            float xs[8] = { e0.x, e0.y, e0.z, e0.w, e1.x, e1.y, e1.z, e1.w };
#pragma unroll
            for (int e = 0; e < 8; e++)
#pragma unroll
                for (int c = 0; c < 8; c++) xp[c] += xs[e] * sWi0[e * 32 + up * 8 + c];

            const float4* q0 = (const float4*)(scr0 + bl * 36 + up * 8);
            float4 ga = q0[0], gb = q0[1];
            float cc0 = sigf(ga.y + xp[1]) * c1s0 + sigf(ga.x + xp[0]) * tanha(ga.z + xp[2]);
            float h10 = sigf(ga.w + xp[3]) * tanha(cc0);
            float cc1 = sigf(gb.y + xp[5]) * c1s1 + sigf(gb.x + xp[4]) * tanha(gb.z + xp[6]);
            float h11 = sigf(gb.w + xp[7]) * tanha(cc1);
            c1s0 = cc0; c1s1 = cc1;
            unsigned hi, lo;
            hilo_pack(h10, h11, hi, lo);
            g_h1hi[rp ^ 1][slot] = hi;
            g_h1lo[rp ^ 1][slot] = lo;

            const float4* q1 = (const float4*)(scr1 + bl * 36 + up * 8);
            float4 ha = q1[0], hb = q1[1];
            float b10 = sB1[up * 8 + 0], b11 = sB1[up * 8 + 1], b12 = sB1[up * 8 + 2], b13 = sB1[up * 8 + 3];
            float b14 = sB1[up * 8 + 4], b15 = sB1[up * 8 + 5], b16 = sB1[up * 8 + 6], b17 = sB1[up * 8 + 7];
            float dd0 = sigf(ha.y + b11) * c2s0 + sigf(ha.x + b10) * tanha(ha.z + b12);
            float h20 = sigf(ha.w + b13) * tanha(dd0);
            float dd1 = sigf(hb.y + b15) * c2s1 + sigf(hb.x + b14) * tanha(hb.z + b16);
            float h21 = sigf(hb.w + b17) * tanha(dd1);
            c2s0 = dd0; c2s1 = dd1;
            hilo_pack(h20, h21, hi, lo);
            g_h2hi[rp][slot] = hi;
            g_h2lo[rp][slot] = lo;
            if (p == myLen - 1) {
                g_last[b * 256 + ug * 8 + 2 * up] = h20;
                g_last[b * 256 + ug * 8 + 2 * up + 1] = h21;
            }
        }
        bar_sync(&g_barG[bg][0], genG, 32);
    }

    bar_sync(&g_barF, genF, NBLK);

    // ---- y = relu(last) @ ff_w^T + ff_b : block = rows 2bid, 2bid+1 ----
    {
        float* sv = (float*)(SB + OFF_H1);
        int br0 = 2 * bid, br1 = 2 * bid + 1;
        sv[tid]       = fmaxf(g_last[br0 * 256 + tid], 0.f);
        sv[256 + tid] = fmaxf(g_last[br1 * 256 + tid], 0.f);
        __syncthreads();
        float a0 = ff_b[tid], a1 = a0;
        const float4* wr = (const float4*)(ff_w + tid * 256);
        const float4* h0 = (const float4*)sv;
        const float4* h1 = (const float4*)(sv + 256);
#pragma unroll 4
        for (int k4 = 0; k4 < 64; k4++) {
            float4 wv = wr[k4];
            float4 hA = h0[k4], hB = h1[k4];
            a0 += wv.x * hA.x + wv.y * hA.y + wv.z * hA.z + wv.w * hA.w;
            a1 += wv.x * hB.x + wv.y * hB.y + wv.z * hB.z + wv.w * hB.w;
        }
        g_y[br0 * 256 + tid] = a0;
        g_y[br1 * 256 + tid] = a1;
    }

    bar_sync(&g_barF, genF, NBLK);

    // ---- BatchNorm over batch: block = cols 2bid, 2bid+1 ----
    {
        float* red = (float*)(SB + OFF_H1);
        for (int r = 0; r < 2; r++) {
            int j = 2 * bid + r;
            float v = g_y[tid * 256 + j];
            __syncthreads();
            red[tid] = v;
            __syncthreads();
            for (int s = 128; s > 0; s >>= 1) {
                if (tid < s) red[tid] += red[tid + s];
                __syncthreads();
            }
            float mean = red[0] * (1.f / 256.f);
            __syncthreads();
            float d = v - mean;
            red[tid] = d * d;
            __syncthreads();
            for (int s = 128; s > 0; s >>= 1) {
                if (tid < s) red[tid] += red[tid + s];
                __syncthreads();
            }
            float inv = rsqrtf(red[0] * (1.f / 256.f) + 1e-5f);
            __syncthreads();
            out[tid * 256 + j] = bn_g[j] * d * inv + bn_b[j];
        }
    }
}

// ---------------- launch ----------------
extern "C" void kernel_launch(void* const* d_in, const int* in_sizes, int n_in,
                              void* d_out, int out_size) {
    const int*   tokens    = (const int*)d_in[0];
    const int*   lengths   = (const int*)d_in[1];
    const float* embedding = (const float*)d_in[2];
    const float* w_ih0     = (const float*)d_in[3];
    const float* w_hh0     = (const float*)d_in[4];
    const float* b_ih0     = (const float*)d_in[5];
    const float* b_hh0     = (const float*)d_in[6];
    const float* w_ih1     = (const float*)d_in[7];
    const float* w_hh1     = (const float*)d_in[8];
    const float* b_ih1     = (const float*)d_in[9];
    const float* b_hh1     = (const float*)d_in[10];
    const float* ff_w      = (const float*)d_in[11];
    const float* ff_b      = (const float*)d_in[12];
    const float* bn_g      = (const float*)d_in[13];
    const float* bn_b      = (const float*)d_in[14];
    float* out = (float*)d_out;

    cudaFuncSetAttribute(lstm_kernel, cudaFuncAttributeMaxDynamicSharedMemorySize,
                         SMEM_DYN);
    prep_kernel<<<256, 256>>>(tokens, embedding);
    lstm_kernel<<<NBLK, TPB, SMEM_DYN>>>(
        lengths, w_ih0, w_hh0, b_ih0, b_hh0,
        w_ih1, w_hh1, b_ih1, b_hh1,
        ff_w, ff_b, bn_g, bn_b, out);
}

// round 10
// speedup vs baseline: 2.0440x; 1.0224x over previous
#include <cuda_runtime.h>
#include <cuda_bf16.h>
#include <math.h>
#include <stdint.h>

#define TPB  256
#define NBLK 128

// ---- smem byte offsets ----
#define OFF_W    0         // 6 x 16384: Wh0hi,Wh0lo,Wi1hi,Wi1lo,Wh1hi,Wh1lo (frag order)
#define OFF_SCR0 98304     // D0 scratch 64*36 floats
#define OFF_SCR1 107520    // D1 partial (ws0)
#define OFF_SCR2 116736    // D1 partial (ws1)
#define OFF_WI0  125952    // 8*32 float
#define OFF_B0   126976    // 32 float
#define OFF_B1   127104    // 32 float
#define SMEM_DYN 127232

// ---------------- device scratch ----------------
// h in A-fragment order: [parity][bg*8192 + (kc*4+mc)*128 + lane*4 + reg] (b32 = bf16x2)
__device__ unsigned g_h1hi[2][32768];
__device__ unsigned g_h1lo[2][32768];
__device__ unsigned g_h2hi[2][32768];
__device__ unsigned g_h2lo[2][32768];
__device__ float    g_last[256 * 256];      // [b][u]
__device__ float    g_y[256 * 256];         // [b][j]
__device__ float    g_emb[256 * 256 * 8];   // [t][b][e]
__device__ unsigned g_barG[4][32];          // per-batch-group barriers
__device__ unsigned g_barF;

// ---------------- helpers ----------------
__device__ __forceinline__ float sigf(float x) { return 1.f / (1.f + __expf(-x)); }
__device__ __forceinline__ float tanha(float x) { return 2.f * sigf(2.f * x) - 1.f; }

__device__ __forceinline__ void hilo_pack(float v0, float v1, unsigned& hi, unsigned& lo) {
    asm("cvt.rn.bf16x2.f32 %0, %1, %2;" : "=r"(hi) : "f"(v1), "f"(v0));  // v0 low
    float l0 = v0 - __uint_as_float(hi << 16);
    float l1 = v1 - __uint_as_float(hi & 0xFFFF0000u);
    asm("cvt.rn.bf16x2.f32 %0, %1, %2;" : "=r"(lo) : "f"(l1), "f"(l0));
}

__device__ __forceinline__ void mma16816(float* acc, uint4 A, unsigned b0, unsigned b1) {
    asm("mma.sync.aligned.m16n8k16.row.col.f32.bf16.bf16.f32 "
        "{%0,%1,%2,%3}, {%4,%5,%6,%7}, {%8,%9}, {%0,%1,%2,%3};"
        : "+f"(acc[0]), "+f"(acc[1]), "+f"(acc[2]), "+f"(acc[3])
        : "r"(A.x), "r"(A.y), "r"(A.z), "r"(A.w), "r"(b0), "r"(b1));
}

__device__ __forceinline__ void bar_sync(unsigned* ctr, unsigned& gen, int n) {
    __syncthreads();
    if (threadIdx.x == 0) {
        __threadfence();
        atomicAdd(ctr, 1u);
        gen += (unsigned)n;
        unsigned v;
        do { asm volatile("ld.acquire.gpu.global.u32 %0, [%1];" : "=r"(v) : "l"(ctr)); }
        while (v < gen);
    }
    __syncthreads();
}

// ---------------- prep ----------------
__global__ void prep_kernel(const int* __restrict__ tokens,
                            const float* __restrict__ emb) {
    int idx = blockIdx.x * 256 + threadIdx.x;
    if (idx < 4) g_barG[idx][0] = 0;
    if (idx == 4) g_barF = 0;
    int b = idx >> 8, t = idx & 255;
    int tok = tokens[b * 256 + t];
    const float4* e = (const float4*)(emb + tok * 8);
    float4* d = (float4*)(g_emb + (t * 256 + b) * 8);
    d[0] = e[0]; d[1] = e[1];
}

// ---------------- persistent LSTM kernel ----------------
extern __shared__ char smem_raw[];

__global__ void __launch_bounds__(TPB, 1)
lstm_kernel(const int* __restrict__ lengths,
            const float* __restrict__ w_ih0, const float* __restrict__ w_hh0,
            const float* __restrict__ b_ih0, const float* __restrict__ b_hh0,
            const float* __restrict__ w_ih1, const float* __restrict__ w_hh1,
            const float* __restrict__ b_ih1, const float* __restrict__ b_hh1,
            const float* __restrict__ ff_w, const float* __restrict__ ff_b,
            const float* __restrict__ bn_g, const float* __restrict__ bn_b,
            float* __restrict__ out) {
    char* SB = smem_raw;
    const int tid = threadIdx.x;
    const int bid = blockIdx.x;
    const int bg = bid >> 5;      // batch group: rows bg*64 .. +63
    const int ug = bid & 31;      // unit group: units ug*8 .. +7
    const int wid = tid >> 5, lane = tid & 31;
    const int wm = wid & 3;       // m16 row block
    const int ws = wid >> 2;      // 0: h1-consumer (D0 + Wi1·h1), 1: h2-consumer (Wh1·h2)
    const int gID = lane >> 2, tig = lane & 3;
    const int bl = tid & 63, up = tid >> 6;     // pointwise: batch row bl, unit pair up
    const int b = bg * 64 + bl;

    float* sWi0 = (float*)(SB + OFF_WI0);
    float* sB0  = (float*)(SB + OFF_B0);
    float* sB1  = (float*)(SB + OFF_B1);
    float* scr0 = (float*)(SB + OFF_SCR0);
    float* scr1 = (float*)(SB + OFF_SCR1);
    float* scr2 = (float*)(SB + OFF_SCR2);

    // ---- pack weights into B-fragment order (bf16 hi/lo) — identical to passing R8 ----
    {
        const float* srcs[3] = { w_hh0, w_ih1, w_hh1 };
#pragma unroll
        for (int m = 0; m < 3; m++) {
            const float* src = srcs[m];
            unsigned* dhi = (unsigned*)(SB + OFF_W + (2 * m) * 16384);
            unsigned* dlo = (unsigned*)(SB + OFF_W + (2 * m + 1) * 16384);
            for (int idx = tid; idx < 4096; idx += TPB) {
                int j = idx & 3, ln = (idx >> 2) & 31, wnn = (idx >> 7) & 1, kc = idx >> 8;
                int n_loc = wnn * 16 + ((j >> 1) << 3) + (ln >> 2);
                int k0 = kc * 16 + (ln & 3) * 2 + (j & 1) * 8;
                int row = (n_loc & 3) * 256 + ug * 8 + (n_loc >> 2);
                float w0 = src[row * 256 + k0], w1 = src[row * 256 + k0 + 1];
                __nv_bfloat16 h0 = __float2bfloat16(w0);
                __nv_bfloat16 h1 = __float2bfloat16(w1);
                __nv_bfloat16 l0 = __float2bfloat16(w0 - __bfloat162float(h0));
                __nv_bfloat16 l1 = __float2bfloat16(w1 - __bfloat162float(h1));
                dhi[idx] = ((unsigned)__bfloat16_as_ushort(h1) << 16) | __bfloat16_as_ushort(h0);
                dlo[idx] = ((unsigned)__bfloat16_as_ushort(l1) << 16) | __bfloat16_as_ushort(l0);
            }
        }
    }
    if (tid < 256) {
        int e = tid >> 5, c = tid & 31;
        int row = (c & 3) * 256 + ug * 8 + (c >> 2);
        sWi0[e * 32 + c] = w_ih0[row * 8 + e];
    }
    if (tid < 32) {
        int row = (tid & 3) * 256 + ug * 8 + (tid >> 2);
        sB0[tid] = b_ih0[row] + b_hh0[row];
        sB1[tid] = b_ih1[row] + b_hh1[row];
    }

    // per-thread h slot in A-frag global layout (identical to R8)
    const int kc_u = ug >> 1;
    const int row16 = bl & 15;
    const int slot = bg * 8192 + (kc_u * 4 + (bl >> 4)) * 128 +
                     ((row16 & 7) * 4 + up) * 4 + (row16 >> 3) + 2 * (ug & 1);

    g_h2hi[1][slot] = 0u;     // h2(-1) = 0
    g_h2lo[1][slot] = 0u;

    const int myLen = lengths[b];
    float c1s0 = 0.f, c1s1 = 0.f, c2s0 = 0.f, c2s1 = 0.f;
    unsigned genG = 0, genF = 0;
    __syncthreads();

    // ---- prologue: h1(0) = cell(x(0), 0) ----
    {
        float xp[8];
#pragma unroll
        for (int c = 0; c < 8; c++) xp[c] = sB0[up * 8 + c];
        const float4* ep = (const float4*)(g_emb + (0 * 256 + b) * 8);
        float4 e0 = ep[0], e1 = ep[1];
        float xs[8] = { e0.x, e0.y, e0.z, e0.w, e1.x, e1.y, e1.z, e1.w };
#pragma unroll
        for (int e = 0; e < 8; e++)
#pragma unroll
            for (int c = 0; c < 8; c++) xp[c] += xs[e] * sWi0[e * 32 + up * 8 + c];
        float cc0 = sigf(xp[0]) * tanha(xp[2]);
        float h10 = sigf(xp[3]) * tanha(cc0);
        float cc1 = sigf(xp[4]) * tanha(xp[6]);
        float h11 = sigf(xp[7]) * tanha(cc1);
        c1s0 = cc0; c1s1 = cc1;
        unsigned hi, lo;
        hilo_pack(h10, h11, hi, lo);
        g_h1hi[0][slot] = hi;
        g_h1lo[0][slot] = lo;
    }
    bar_sync(&g_barG[bg][0], genG, 32);

    // A-frag base (uint4 units): bg*2048 + wm*32 + lane; kc stride = 128
    const int abase = bg * 2048 + wm * 32 + lane;
    const char* pW0 = SB + OFF_W + 0 * 16384 + lane * 16;
    const char* pW1 = SB + OFF_W + 1 * 16384 + lane * 16;
    const char* pW2 = SB + OFF_W + 2 * 16384 + lane * 16;
    const char* pW3 = SB + OFF_W + 3 * 16384 + lane * 16;
    const char* pW4 = SB + OFF_W + 4 * 16384 + lane * 16;
    const char* pW5 = SB + OFF_W + 5 * 16384 + lane * 16;

    // ---- main loop: phase p computes h1(p+1) and h2(p) ----
    for (int p = 0; p < 256; p++) {
        const int rp = p & 1;

        if (ws == 0) {
            // D0 = h1·Wh0ᵀ (3 terms), D1p = h1·Wi1ᵀ (3 terms)
            const uint4* a1h = (const uint4*)g_h1hi[rp] + abase;
            const uint4* a1l = (const uint4*)g_h1lo[rp] + abase;
            float D0[16], D1[16];
#pragma unroll
            for (int i = 0; i < 16; i++) { D0[i] = 0.f; D1[i] = 0.f; }
#pragma unroll 4
            for (int kc = 0; kc < 16; kc++) {
                uint4 Ah = __ldcg(a1h + kc * 128);
                uint4 Al = __ldcg(a1l + kc * 128);
#pragma unroll
                for (int hf = 0; hf < 2; hf++) {
                    uint4 B0h = *(const uint4*)(pW0 + kc * 1024 + hf * 512);
                    uint4 B0l = *(const uint4*)(pW1 + kc * 1024 + hf * 512);
                    uint4 B1h = *(const uint4*)(pW2 + kc * 1024 + hf * 512);
                    uint4 B1l = *(const uint4*)(pW3 + kc * 1024 + hf * 512);
                    float* d0 = D0 + hf * 8;
                    float* d1 = D1 + hf * 8;
                    mma16816(d0 + 0, Ah, B0h.x, B0h.y); mma16816(d0 + 4, Ah, B0h.z, B0h.w);
                    mma16816(d1 + 0, Ah, B1h.x, B1h.y); mma16816(d1 + 4, Ah, B1h.z, B1h.w);
                    mma16816(d0 + 0, Ah, B0l.x, B0l.y); mma16816(d0 + 4, Ah, B0l.z, B0l.w);
                    mma16816(d1 + 0, Ah, B1l.x, B1l.y); mma16816(d1 + 4, Ah, B1l.z, B1l.w);
                    mma16816(d0 + 0, Al, B0h.x, B0h.y); mma16816(d0 + 4, Al, B0h.z, B0h.w);
                    mma16816(d1 + 0, Al, B1h.x, B1h.y); mma16816(d1 + 4, Al, B1h.z, B1h.w);
                }
            }
            // dump (no sync needed first: scr consumed last step before bar)
            int r0 = wm * 16 + gID;
#pragma unroll
            for (int hf = 0; hf < 2; hf++)
#pragma unroll
                for (int blk = 0; blk < 2; blk++) {
                    int c0 = hf * 16 + blk * 8 + tig * 2;
                    int ib = hf * 8 + blk * 4;
                    scr0[r0 * 36 + c0] = D0[ib];           scr0[r0 * 36 + c0 + 1] = D0[ib + 1];
                    scr0[(r0 + 8) * 36 + c0] = D0[ib + 2]; scr0[(r0 + 8) * 36 + c0 + 1] = D0[ib + 3];
                    scr1[r0 * 36 + c0] = D1[ib];           scr1[r0 * 36 + c0 + 1] = D1[ib + 1];
                    scr1[(r0 + 8) * 36 + c0] = D1[ib + 2]; scr1[(r0 + 8) * 36 + c0 + 1] = D1[ib + 3];
                }
        } else {
            // D1q = h2·Wh1ᵀ (3 terms)
            const uint4* a2h = (const uint4*)g_h2hi[rp ^ 1] + abase;
            const uint4* a2l = (const uint4*)g_h2lo[rp ^ 1] + abase;
            float D2[16];
#pragma unroll
            for (int i = 0; i < 16; i++) D2[i] = 0.f;
#pragma unroll 4
            for (int kc = 0; kc < 16; kc++) {
                uint4 Ah = __ldcg(a2h + kc * 128);
                uint4 Al = __ldcg(a2l + kc * 128);
#pragma unroll
                for (int hf = 0; hf < 2; hf++) {
                    uint4 B2h = *(const uint4*)(pW4 + kc * 1024 + hf * 512);
                    uint4 B2l = *(const uint4*)(pW5 + kc * 1024 + hf * 512);
                    float* d2 = D2 + hf * 8;
                    mma16816(d2 + 0, Ah, B2h.x, B2h.y); mma16816(d2 + 4, Ah, B2h.z, B2h.w);
                    mma16816(d2 + 0, Ah, B2l.x, B2l.y); mma16816(d2 + 4, Ah, B2l.z, B2l.w);
                    mma16816(d2 + 0, Al, B2h.x, B2h.y); mma16816(d2 + 4, Al, B2h.z, B2h.w);
                }
            }
            int r0 = wm * 16 + gID;
#pragma unroll
            for (int hf = 0; hf < 2; hf++)
#pragma unroll
                for (int blk = 0; blk < 2; blk++) {
                    int c0 = hf * 16 + blk * 8 + tig * 2;
                    int ib = hf * 8 + blk * 4;
                    scr2[r0 * 36 + c0] = D2[ib];           scr2[r0 * 36 + c0 + 1] = D2[ib + 1];
                    scr2[(r0 + 8) * 36 + c0] = D2[ib + 2]; scr2[(r0 + 8) * 36 + c0 + 1] = D2[ib + 3];
                }
        }

        // x-part for h1(p+1) — independent of scratch, overlaps other warps' mma tail
        int tx = (p < 255) ? p + 1 : 255;
        float xp[8];
#pragma unroll
        for (int c = 0; c < 8; c++) xp[c] = sB0[up * 8 + c];
        {
            const float4* ep = (const float4*)(g_emb + (tx * 256 + b) * 8);
            float4 e0 = ep[0], e1 = ep[1];
            float xs[8] = { e0.x, e0.y, e0.z, e0.w, e1.x, e1.y, e1.z, e1.w };
#pragma unroll
            for (int e = 0; e < 8; e++)
#pragma unroll
                for (int c = 0; c < 8; c++) xp[c] += xs[e] * sWi0[e * 32 + up * 8 + c];
        }

        __syncthreads();   // all dumps visible

        // ---- pointwise: thread owns (bl, units 2up, 2up+1) ----
        {
            const float4* q0 = (const float4*)(scr0 + bl * 36 + up * 8);
            float4 ga = q0[0], gb = q0[1];
            float cc0 = sigf(ga.y + xp[1]) * c1s0 + sigf(ga.x + xp[0]) * tanha(ga.z + xp[2]);
            float h10 = sigf(ga.w + xp[3]) * tanha(cc0);
            float cc1 = sigf(gb.y + xp[5]) * c1s1 + sigf(gb.x + xp[4]) * tanha(gb.z + xp[6]);
            float h11 = sigf(gb.w + xp[7]) * tanha(cc1);
            c1s0 = cc0; c1s1 = cc1;
            unsigned hi, lo;
            hilo_pack(h10, h11, hi, lo);
            g_h1hi[rp ^ 1][slot] = hi;
            g_h1lo[rp ^ 1][slot] = lo;

            const float4* qa = (const float4*)(scr1 + bl * 36 + up * 8);
            const float4* qb = (const float4*)(scr2 + bl * 36 + up * 8);
            float4 ha = qa[0], h2a = qb[0];
            float4 hb = qa[1], h2b = qb[1];
            float g0 = ha.x + h2a.x + sB1[up * 8 + 0];
            float g1 = ha.y + h2a.y + sB1[up * 8 + 1];
            float g2 = ha.z + h2a.z + sB1[up * 8 + 2];
            float g3 = ha.w + h2a.w + sB1[up * 8 + 3];
            float g4 = hb.x + h2b.x + sB1[up * 8 + 4];
            float g5 = hb.y + h2b.y + sB1[up * 8 + 5];
            float g6 = hb.z + h2b.z + sB1[up * 8 + 6];
            float g7 = hb.w + h2b.w + sB1[up * 8 + 7];
            float dd0 = sigf(g1) * c2s0 + sigf(g0) * tanha(g2);
            float h20 = sigf(g3) * tanha(dd0);
            float dd1 = sigf(g5) * c2s1 + sigf(g4) * tanha(g6);
            float h21 = sigf(g7) * tanha(dd1);
            c2s0 = dd0; c2s1 = dd1;
            hilo_pack(h20, h21, hi, lo);
            g_h2hi[rp][slot] = hi;
            g_h2lo[rp][slot] = lo;
            if (p == myLen - 1) {
                g_last[b * 256 + ug * 8 + 2 * up] = h20;
                g_last[b * 256 + ug * 8 + 2 * up + 1] = h21;
            }
        }
        bar_sync(&g_barG[bg][0], genG, 32);
    }

    bar_sync(&g_barF, genF, NBLK);

    // ---- y = relu(last) @ ff_w^T + ff_b : block = rows 2bid, 2bid+1 ----
    {
        float* sv = scr0;
        int br0 = 2 * bid, br1 = 2 * bid + 1;
        sv[tid]       = fmaxf(g_last[br0 * 256 + tid], 0.f);
        sv[256 + tid] = fmaxf(g_last[br1 * 256 + tid], 0.f);
        __syncthreads();
        float a0 = ff_b[tid], a1 = a0;
        const float4* wr = (const float4*)(ff_w + tid * 256);
        const float4* h0 = (const float4*)sv;
        const float4* h1 = (const float4*)(sv + 256);
#pragma unroll 4
        for (int k4 = 0; k4 < 64; k4++) {
            float4 wv = wr[k4];
            float4 hA = h0[k4], hB = h1[k4];
            a0 += wv.x * hA.x + wv.y * hA.y + wv.z * hA.z + wv.w * hA.w;
            a1 += wv.x * hB.x + wv.y * hB.y + wv.z * hB.z + wv.w * hB.w;
        }
        g_y[br0 * 256 + tid] = a0;
        g_y[br1 * 256 + tid] = a1;
    }

    bar_sync(&g_barF, genF, NBLK);

    // ---- BatchNorm over batch: block = cols 2bid, 2bid+1 ----
    {
        float* red = scr0;
        for (int r = 0; r < 2; r++) {
            int j = 2 * bid + r;
            float v = g_y[tid * 256 + j];
            __syncthreads();
            red[tid] = v;
            __syncthreads();
            for (int s = 128; s > 0; s >>= 1) {
                if (tid < s) red[tid] += red[tid + s];
                __syncthreads();
            }
            float mean = red[0] * (1.f / 256.f);
            __syncthreads();
            float d = v - mean;
            red[tid] = d * d;
            __syncthreads();
            for (int s = 128; s > 0; s >>= 1) {
                if (tid < s) red[tid] += red[tid + s];
                __syncthreads();
            }
            float inv = rsqrtf(red[0] * (1.f / 256.f) + 1e-5f);
            __syncthreads();
            out[tid * 256 + j] = bn_g[j] * d * inv + bn_b[j];
        }
    }
}

// ---------------- launch ----------------
extern "C" void kernel_launch(void* const* d_in, const int* in_sizes, int n_in,
                              void* d_out, int out_size) {
    const int*   tokens    = (const int*)d_in[0];
    const int*   lengths   = (const int*)d_in[1];
    const float* embedding = (const float*)d_in[2];
    const float* w_ih0     = (const float*)d_in[3];
    const float* w_hh0     = (const float*)d_in[4];
    const float* b_ih0     = (const float*)d_in[5];
    const float* b_hh0     = (const float*)d_in[6];
    const float* w_ih1     = (const float*)d_in[7];
    const float* w_hh1     = (const float*)d_in[8];
    const float* b_ih1     = (const float*)d_in[9];
    const float* b_hh1     = (const float*)d_in[10];
    const float* ff_w      = (const float*)d_in[11];
    const float* ff_b      = (const float*)d_in[12];
    const float* bn_g      = (const float*)d_in[13];
    const float* bn_b      = (const float*)d_in[14];
    float* out = (float*)d_out;

    cudaFuncSetAttribute(lstm_kernel, cudaFuncAttributeMaxDynamicSharedMemorySize,
                         SMEM_DYN);
    prep_kernel<<<256, 256>>>(tokens, embedding);
    lstm_kernel<<<NBLK, TPB, SMEM_DYN>>>(
        lengths, w_ih0, w_hh0, b_ih0, b_hh0,
        w_ih1, w_hh1, b_ih1, b_hh1,
        ff_w, ff_b, bn_g, bn_b, out);
}